// round 2
// baseline (speedup 1.0000x reference)
#include <cuda_runtime.h>

// GLRFast forward: out[b,g,c,h,w] = patchs - sum_e ew[b,g,e,h,w] * nbr_e(patchs)
// nbr order (DELTAS): e0=(-1,0) up, e1=(0,-1) left, e2=(0,1) right, e3=(1,0) down
// Replicate ('edge') padding on H and W borders.
// Shapes: B=4, G=8, C=32, H=128, W=128 (fp32). node_degree (d_in[2]) unused.

#define H_DIM 128
#define W_DIM 128
#define C_DIM 32
#define ROWS_PER_BLOCK 8
#define C_PER_BLOCK 8

__global__ __launch_bounds__(256) void glrfast_kernel(
    const float* __restrict__ patchs,
    const float* __restrict__ ew,
    float* __restrict__ out)
{
    const int lane = threadIdx.x;                         // 0..31 -> one full row per warp
    const int h    = blockIdx.x * ROWS_PER_BLOCK + threadIdx.y;
    const int c0   = blockIdx.y * C_PER_BLOCK;
    const int bg   = blockIdx.z;                          // 0..31 (= b*G + g)
    const int w0   = lane * 4;

    const int HW = H_DIM * W_DIM;

    // Edge weights for this pixel quad: [bg, e, h, w0..w0+3]
    const float* ewb = ew + ((long)bg * 4) * HW + (long)h * W_DIM + w0;
    const float4 eN = *(const float4*)(ewb + 0L * HW);
    const float4 eW = *(const float4*)(ewb + 1L * HW);
    const float4 eE = *(const float4*)(ewb + 2L * HW);
    const float4 eS = *(const float4*)(ewb + 3L * HW);

    const int hu = (h > 0)         ? h - 1 : 0;           // replicate pad
    const int hd = (h < H_DIM - 1) ? h + 1 : H_DIM - 1;

    const float* pb = patchs + ((long)bg * C_DIM + c0) * HW;
    float*       ob = out    + ((long)bg * C_DIM + c0) * HW;

    const long off_c  = (long)h  * W_DIM + w0;
    const long off_u  = (long)hu * W_DIM + w0;
    const long off_d  = (long)hd * W_DIM + w0;

#pragma unroll
    for (int cc = 0; cc < C_PER_BLOCK; ++cc) {
        const float* pc = pb + (long)cc * HW;

        const float4 cen = *(const float4*)(pc + off_c);
        const float4 up  = *(const float4*)(pc + off_u);
        const float4 dn  = *(const float4*)(pc + off_d);

        // w-direction neighbors via in-warp shuffles (warp == one row)
        float xm1 = __shfl_up_sync(0xffffffffu, cen.w, 1);   // x[w0-1]
        if (lane == 0)  xm1 = cen.x;                          // replicate x[0]
        float xp4 = __shfl_down_sync(0xffffffffu, cen.x, 1); // x[w0+4]
        if (lane == 31) xp4 = cen.w;                          // replicate x[127]

        float4 o;
        o.x = cen.x - (eN.x * up.x + eW.x * xm1   + eE.x * cen.y + eS.x * dn.x);
        o.y = cen.y - (eN.y * up.y + eW.y * cen.x + eE.y * cen.z + eS.y * dn.y);
        o.z = cen.z - (eN.z * up.z + eW.z * cen.y + eE.z * cen.w + eS.z * dn.z);
        o.w = cen.w - (eN.w * up.w + eW.w * cen.z + eE.w * xp4   + eS.w * dn.w);

        *(float4*)(ob + (long)cc * HW + off_c) = o;
    }
}

extern "C" void kernel_launch(void* const* d_in, const int* in_sizes, int n_in,
                              void* d_out, int out_size)
{
    const float* patchs = (const float*)d_in[0];   // [4,8,32,128,128]
    const float* ew     = (const float*)d_in[1];   // [4,8,4,128,128]
    // d_in[2] = node_degree: unused in forward
    float* out = (float*)d_out;                    // [4,8,32,128,128]

    dim3 block(32, ROWS_PER_BLOCK);                           // 256 threads
    dim3 grid(H_DIM / ROWS_PER_BLOCK,                         // 16 h-tiles
              C_DIM / C_PER_BLOCK,                            // 4 c-chunks
              32);                                            // B*G planes

    glrfast_kernel<<<grid, block>>>(patchs, ew, out);
}

// round 3
// speedup vs baseline: 1.0011x; 1.0011x over previous
#include <cuda_runtime.h>

// GLRFast forward: out[b,g,c,h,w] = patchs - sum_e ew[b,g,e,h,w] * nbr_e(patchs)
// nbr order (DELTAS): e0=(-1,0) up, e1=(0,-1) left, e2=(0,1) right, e3=(1,0) down
// Replicate ('edge') padding on H and W borders.
// Shapes: B=4, G=8, C=32, H=128, W=128 (fp32). node_degree (d_in[2]) unused.

#define H_DIM 128
#define W_DIM 128
#define C_DIM 32
#define ROWS_PER_BLOCK 8
#define C_PER_BLOCK 8

__global__ __launch_bounds__(256) void glrfast_kernel(
    const float* __restrict__ patchs,
    const float* __restrict__ ew,
    float* __restrict__ out)
{
    const int lane = threadIdx.x;                         // 0..31 -> one full row per warp
    const int h    = blockIdx.x * ROWS_PER_BLOCK + threadIdx.y;
    const int c0   = blockIdx.y * C_PER_BLOCK;
    const int bg   = blockIdx.z;                          // 0..31 (= b*G + g)
    const int w0   = lane * 4;

    const int HW = H_DIM * W_DIM;

    // Edge weights for this pixel quad: [bg, e, h, w0..w0+3]
    const float* ewb = ew + ((long)bg * 4) * HW + (long)h * W_DIM + w0;
    const float4 eN = *(const float4*)(ewb + 0L * HW);
    const float4 eW = *(const float4*)(ewb + 1L * HW);
    const float4 eE = *(const float4*)(ewb + 2L * HW);
    const float4 eS = *(const float4*)(ewb + 3L * HW);

    const int hu = (h > 0)         ? h - 1 : 0;           // replicate pad
    const int hd = (h < H_DIM - 1) ? h + 1 : H_DIM - 1;

    const float* pb = patchs + ((long)bg * C_DIM + c0) * HW;
    float*       ob = out    + ((long)bg * C_DIM + c0) * HW;

    const long off_c  = (long)h  * W_DIM + w0;
    const long off_u  = (long)hu * W_DIM + w0;
    const long off_d  = (long)hd * W_DIM + w0;

#pragma unroll
    for (int cc = 0; cc < C_PER_BLOCK; ++cc) {
        const float* pc = pb + (long)cc * HW;

        const float4 cen = *(const float4*)(pc + off_c);
        const float4 up  = *(const float4*)(pc + off_u);
        const float4 dn  = *(const float4*)(pc + off_d);

        // w-direction neighbors via in-warp shuffles (warp == one row)
        float xm1 = __shfl_up_sync(0xffffffffu, cen.w, 1);   // x[w0-1]
        if (lane == 0)  xm1 = cen.x;                          // replicate x[0]
        float xp4 = __shfl_down_sync(0xffffffffu, cen.x, 1); // x[w0+4]
        if (lane == 31) xp4 = cen.w;                          // replicate x[127]

        float4 o;
        o.x = cen.x - (eN.x * up.x + eW.x * xm1   + eE.x * cen.y + eS.x * dn.x);
        o.y = cen.y - (eN.y * up.y + eW.y * cen.x + eE.y * cen.z + eS.y * dn.y);
        o.z = cen.z - (eN.z * up.z + eW.z * cen.y + eE.z * cen.w + eS.z * dn.z);
        o.w = cen.w - (eN.w * up.w + eW.w * cen.z + eE.w * xp4   + eS.w * dn.w);

        *(float4*)(ob + (long)cc * HW + off_c) = o;
    }
}

extern "C" void kernel_launch(void* const* d_in, const int* in_sizes, int n_in,
                              void* d_out, int out_size)
{
    const float* patchs = (const float*)d_in[0];   // [4,8,32,128,128]
    const float* ew     = (const float*)d_in[1];   // [4,8,4,128,128]
    // d_in[2] = node_degree: unused in forward
    float* out = (float*)d_out;                    // [4,8,32,128,128]

    dim3 block(32, ROWS_PER_BLOCK);                           // 256 threads
    dim3 grid(H_DIM / ROWS_PER_BLOCK,                         // 16 h-tiles
              C_DIM / C_PER_BLOCK,                            // 4 c-chunks
              32);                                            // B*G planes

    glrfast_kernel<<<grid, block>>>(patchs, ew, out);
}